// round 1
// baseline (speedup 1.0000x reference)
#include <cuda_runtime.h>
#include <math.h>
#include <stdint.h>

#define NN 50000
#define EE 800000
#define ENT (EE + NN)
#define NH 8
#define PH 16
#define DH 128
#define D0 56
#define NC 7
#define NL 3

// ---------------- scratch (device globals; no allocation) ----------------
__device__ int   g_deg[NN];
__device__ int   g_off[NN + 1];
__device__ int   g_cur[NN];
__device__ int   g_srcs[ENT];
__device__ float g_norm[ENT];
__device__ float g_dinv[NN];
__device__ float g_hB[NN * D0];    // 56-dim node features
__device__ float g_hA[NN * PH];    // 16-dim node features (GAT output)
__device__ float g_agg[NN * D0];   // aggregated pre-GEMM features
__device__ float g_x1[NN * DH];    // GCN output / GAT input (also XW0 @ stride 56)
__device__ float g_x2[NN * DH];    // hh = h @ gat_w
__device__ float g_es[NN * NH];
__device__ float g_ed[NN * NH];
__device__ float g_m[NN * NH];
__device__ float g_ri[NN * NH];

// ---------------- CSR construction ----------------
__global__ void k_deg_init() {
    int i = blockIdx.x * blockDim.x + threadIdx.x;
    if (i < NN) g_deg[i] = 1;  // self-loop
}

__global__ void k_deg_count(const int* __restrict__ ei) {
    int e = blockIdx.x * blockDim.x + threadIdx.x;
    if (e < EE) atomicAdd(&g_deg[ei[EE + e]], 1);
}

__global__ void k_scan() {  // 1 block, 1024 threads
    __shared__ int ssum[1024];
    int tid = threadIdx.x;
    const int chunk = (NN + 1023) / 1024;
    int base = tid * chunk;
    int s = 0;
    for (int i = 0; i < chunk; i++) {
        int idx = base + i;
        if (idx < NN) s += g_deg[idx];
    }
    ssum[tid] = s;
    __syncthreads();
    for (int off = 1; off < 1024; off <<= 1) {
        int v = (tid >= off) ? ssum[tid - off] : 0;
        __syncthreads();
        ssum[tid] += v;
        __syncthreads();
    }
    if (tid == 0) g_off[NN] = ssum[1023];
    int run = tid ? ssum[tid - 1] : 0;
    for (int i = 0; i < chunk; i++) {
        int idx = base + i;
        if (idx < NN) {
            g_off[idx] = run;
            g_cur[idx] = run;
            g_dinv[idx] = rsqrtf((float)g_deg[idx]);
            run += g_deg[idx];
        }
    }
}

__global__ void k_fill(const int* __restrict__ ei) {
    int e = blockIdx.x * blockDim.x + threadIdx.x;
    if (e >= ENT) return;
    int s, d;
    if (e < EE) { s = ei[e]; d = ei[EE + e]; }
    else        { s = d = e - EE; }
    int p = atomicAdd(&g_cur[d], 1);
    g_srcs[p] = s;
    g_norm[p] = g_dinv[s] * g_dinv[d];
}

// ---------------- GEMM0: x[N,1433] @ w_feat[1433,56] -> g_x1 (stride 56) ----------------
__global__ void k_gemm0(const float* __restrict__ x, const float* __restrict__ w) {
    __shared__ float xs[64 * 16];
    __shared__ float ws[16 * 56];
    int tx = threadIdx.x;             // 0..55 (col)
    int ty = threadIdx.y;             // 0..3
    int tid = ty * 56 + tx;           // 0..223
    int row0 = blockIdx.x * 64;
    float acc[16];
#pragma unroll
    for (int r = 0; r < 16; r++) acc[r] = 0.f;
    for (int kt = 0; kt < 1433; kt += 16) {
        for (int i = tid; i < 64 * 16; i += 224) {
            int r = i >> 4, kk = i & 15;
            int gk = kt + kk, gr = row0 + r;
            xs[i] = (gk < 1433 && gr < NN) ? x[(int64_t)gr * 1433 + gk] : 0.f;
        }
        for (int i = tid; i < 16 * 56; i += 224) {
            int kk = i / 56, c = i - kk * 56;
            int gk = kt + kk;
            ws[i] = (gk < 1433) ? w[gk * 56 + c] : 0.f;
        }
        __syncthreads();
#pragma unroll
        for (int kk = 0; kk < 16; kk++) {
            float wv = ws[kk * 56 + tx];
#pragma unroll
            for (int r = 0; r < 16; r++)
                acc[r] += xs[(ty * 16 + r) * 16 + kk] * wv;
        }
        __syncthreads();
    }
#pragma unroll
    for (int r = 0; r < 16; r++) {
        int gr = row0 + ty * 16 + r;
        if (gr < NN) g_x1[gr * 56 + tx] = acc[r];
    }
}

// ---------------- GCN aggregation: out[d,:] = sum_e norm * in[src,:]  (warp/dst) ----------------
__global__ void k_agg(const float* __restrict__ in, int din, float* __restrict__ out,
                      const float* __restrict__ bias, int do_relu) {
    int w = (blockIdx.x * blockDim.x + threadIdx.x) >> 5;
    int lane = threadIdx.x & 31;
    if (w >= NN) return;
    int e0 = g_off[w], e1 = g_off[w + 1];
    int c1 = lane + 32;
    float a0 = 0.f, a1 = 0.f;
    for (int e = e0; e < e1; e++) {
        int s = g_srcs[e];
        float nm = g_norm[e];
        const float* rp = in + s * din;
        if (lane < din) a0 += nm * rp[lane];
        if (c1 < din)   a1 += nm * rp[c1];
    }
    if (lane < din) {
        float v = a0 + (bias ? bias[lane] : 0.f);
        if (do_relu) v = fmaxf(v, 0.f);
        out[w * din + lane] = v;
    }
    if (c1 < din) {
        float v = a1 + (bias ? bias[c1] : 0.f);
        if (do_relu) v = fmaxf(v, 0.f);
        out[w * din + c1] = v;
    }
}

// ---------------- GCN GEMM + bias + relu: [8 nodes/block] agg[.,din] @ W[din,128] ----------------
__global__ void k_gcn_gemm(const float* __restrict__ agg, int din, const float* __restrict__ W,
                           const float* __restrict__ b, float* __restrict__ out) {
    __shared__ float hs[8 * 64];
    int j = threadIdx.x;
    int n0 = blockIdx.x * 8;
    for (int i = j; i < 8 * din; i += 128) {
        int r = i / din, k = i - r * din;
        hs[r * 64 + k] = agg[(n0 + r) * din + k];
    }
    __syncthreads();
    float bv = b[j];
    float acc[8];
#pragma unroll
    for (int r = 0; r < 8; r++) acc[r] = bv;
    for (int k = 0; k < din; k++) {
        float wv = W[k * 128 + j];
#pragma unroll
        for (int r = 0; r < 8; r++) acc[r] += hs[r * 64 + k] * wv;
    }
#pragma unroll
    for (int r = 0; r < 8; r++) {
        float v = acc[r];
        out[(n0 + r) * 128 + j] = v > 0.f ? v : 0.f;
    }
}

// ---------------- GAT GEMM: hh = h @ gat_w; fused e_s/e_d epilogue ----------------
__global__ void k_gat_gemm(const float* __restrict__ hin, const float* __restrict__ W,
                           const float* __restrict__ asrc, const float* __restrict__ adst) {
    __shared__ float hs[8 * 128];
    int j = threadIdx.x;
    int n0 = blockIdx.x * 8;
    for (int i = j; i < 8 * 128; i += 128) hs[i] = hin[n0 * 128 + i];
    __syncthreads();
    float acc[8];
#pragma unroll
    for (int r = 0; r < 8; r++) acc[r] = 0.f;
    for (int k = 0; k < 128; k++) {
        float wv = W[k * 128 + j];
#pragma unroll
        for (int r = 0; r < 8; r++) acc[r] += hs[r * 128 + k] * wv;
    }
    float av = asrc[j], dv = adst[j];
    int head = j >> 4;
#pragma unroll
    for (int r = 0; r < 8; r++) {
        g_x2[(n0 + r) * 128 + j] = acc[r];
        float vs = acc[r] * av;
        float vd = acc[r] * dv;
#pragma unroll
        for (int off = 8; off > 0; off >>= 1) {
            vs += __shfl_xor_sync(0xffffffffu, vs, off);
            vd += __shfl_xor_sync(0xffffffffu, vd, off);
        }
        if ((j & 15) == 0) {
            g_es[(n0 + r) * NH + head] = vs;
            g_ed[(n0 + r) * NH + head] = vd;
        }
    }
}

// ---------------- GAT pass1: online softmax stats per (dst, head) ----------------
__global__ void k_pass1() {
    int t = blockIdx.x * blockDim.x + threadIdx.x;
    if (t >= NN * NH) return;
    int d = t >> 3, h = t & 7;
    float ed = g_ed[t];
    int e0 = g_off[d], e1 = g_off[d + 1];
    float m = -1e30f, s = 0.f;
    for (int e = e0; e < e1; e++) {
        int sr = g_srcs[e];
        float v = g_es[sr * NH + h] + ed;
        v = v > 0.f ? v : 0.2f * v;
        if (v <= m) {
            s += __expf(v - m);
        } else {
            s = s * __expf(m - v) + 1.f;
            m = v;
        }
    }
    g_m[t] = m;
    g_ri[t] = 1.f / s;
}

// ---------------- GAT pass2: weighted aggregate + head-mean + bias (warp/dst) ----------------
__global__ void k_pass2(const float* __restrict__ gb) {
    int w = (blockIdx.x * blockDim.x + threadIdx.x) >> 5;
    int lane = threadIdx.x & 31;
    if (w >= NN) return;
    float mh = 0.f, rih = 0.f, edh = 0.f;
    if (lane < 8) {
        mh = g_m[w * NH + lane];
        rih = g_ri[w * NH + lane];
        edh = g_ed[w * NH + lane];
    }
    int e0 = g_off[w], e1 = g_off[w + 1];
    float a0 = 0.f, a1 = 0.f, a2 = 0.f, a3 = 0.f;
    int h0 = lane >> 4;  // 0 or 1
    for (int e = e0; e < e1; e++) {
        int s = g_srcs[e];
        float wv = 0.f;
        if (lane < 8) {
            float v = g_es[s * NH + lane] + edh;
            v = v > 0.f ? v : 0.2f * v;
            wv = __expf(v - mh) * rih;
        }
        const float* hp = g_x2 + s * 128;
        float w0 = __shfl_sync(0xffffffffu, wv, h0);
        float w1 = __shfl_sync(0xffffffffu, wv, h0 + 2);
        float w2 = __shfl_sync(0xffffffffu, wv, h0 + 4);
        float w3 = __shfl_sync(0xffffffffu, wv, h0 + 6);
        a0 += w0 * hp[lane];
        a1 += w1 * hp[lane + 32];
        a2 += w2 * hp[lane + 64];
        a3 += w3 * hp[lane + 96];
    }
    float s4 = a0 + a1 + a2 + a3;
    s4 += __shfl_xor_sync(0xffffffffu, s4, 16);
    if (lane < 16) g_hA[w * PH + lane] = s4 * 0.125f + gb[lane];
}

// ---------------- MAS: g_hB = g_hA @ mas_w[16,56] + mas_b ----------------
__global__ void k_mas(const float* __restrict__ W, const float* __restrict__ b) {
    __shared__ float hs[16];
    int n = blockIdx.x;
    int j = threadIdx.x;
    if (j < 16) hs[j] = g_hA[n * PH + j];
    __syncthreads();
    if (j < D0) {
        float acc = b[j];
#pragma unroll
        for (int k = 0; k < 16; k++) acc += hs[k] * W[k * D0 + j];
        g_hB[n * D0 + j] = acc;
    }
}

// ---------------- output: d_out = g_hB @ out_w[56,7] + out_b ----------------
__global__ void k_out(const float* __restrict__ W, const float* __restrict__ b,
                      float* __restrict__ out) {
    int t = blockIdx.x * blockDim.x + threadIdx.x;
    if (t >= NN * NC) return;
    int n = t / NC, c = t - n * NC;
    float acc = b[c];
    const float* hr = g_hB + n * D0;
#pragma unroll
    for (int k = 0; k < D0; k++) acc += hr[k] * W[k * NC + c];
    out[t] = acc;
}

// ---------------- launcher ----------------
extern "C" void kernel_launch(void* const* d_in, const int* in_sizes, int n_in,
                              void* d_out, int out_size) {
    const float* x      = (const float*)d_in[0];
    const int*   ei     = (const int*)d_in[1];
    const float* w_feat = (const float*)d_in[2];
    const float* b_feat = (const float*)d_in[3];
    const float* gcn0_w = (const float*)d_in[4];
    const float* gcn0_b = (const float*)d_in[5];
    const float* gcn_w  = (const float*)d_in[6];
    const float* gcn_b  = (const float*)d_in[7];
    const float* gat_w  = (const float*)d_in[8];
    const float* gat_as = (const float*)d_in[9];
    const float* gat_ad = (const float*)d_in[10];
    const float* gat_b  = (const float*)d_in[11];
    const float* mas_w  = (const float*)d_in[12];
    const float* mas_b  = (const float*)d_in[13];
    const float* out_w  = (const float*)d_in[14];
    const float* out_b  = (const float*)d_in[15];
    float* out = (float*)d_out;
    (void)in_sizes; (void)n_in; (void)out_size;

    float *p_x1, *p_hA, *p_hB, *p_agg;
    cudaGetSymbolAddress((void**)&p_x1, g_x1);
    cudaGetSymbolAddress((void**)&p_hA, g_hA);
    cudaGetSymbolAddress((void**)&p_hB, g_hB);
    cudaGetSymbolAddress((void**)&p_agg, g_agg);

    // CSR build
    k_deg_init<<<(NN + 255) / 256, 256>>>();
    k_deg_count<<<(EE + 255) / 256, 256>>>(ei);
    k_scan<<<1, 1024>>>();
    k_fill<<<(ENT + 255) / 256, 256>>>(ei);

    // GNFE: transform (1433->56) then aggregate (+bias, relu)
    k_gemm0<<<(NN + 63) / 64, dim3(56, 4)>>>(x, w_feat);
    k_agg<<<NN / 8, 256>>>(p_x1, D0, p_hB, b_feat, 1);

    for (int m = 0; m < NL; m++) {
        for (int i = 0; i < NL; i++) {
            int din = i ? PH : D0;
            const float* hin = i ? p_hA : p_hB;
            const float* Wg = i ? (gcn_w + (m * (NL - 1) + (i - 1)) * PH * DH)
                                : (gcn0_w + m * D0 * DH);
            const float* bg = i ? (gcn_b + (m * (NL - 1) + (i - 1)) * DH)
                                : (gcn0_b + m * DH);
            int li = m * NL + i;
            // GCN: aggregate first (linear), then GEMM + bias + relu
            k_agg<<<NN / 8, 256>>>(hin, din, p_agg, (const float*)0, 0);
            k_gcn_gemm<<<NN / 8, 128>>>(p_agg, din, Wg, bg, p_x1);
            // GAT
            k_gat_gemm<<<NN / 8, 128>>>(p_x1, gat_w + li * DH * DH,
                                        gat_as + li * NH * PH, gat_ad + li * NH * PH);
            k_pass1<<<(NN * NH + 255) / 256, 256>>>();
            k_pass2<<<NN / 8, 256>>>(gat_b + li * PH);
        }
        k_mas<<<NN, 64>>>(mas_w + m * PH * D0, mas_b + m * D0);
    }
    k_out<<<(NN * NC + 255) / 256, 256>>>(out_w, out_b, out);
}

// round 2
// speedup vs baseline: 1.1569x; 1.1569x over previous
#include <cuda_runtime.h>
#include <math.h>
#include <stdint.h>

#define NN 50000
#define EE 800000
#define ENT (EE + NN)
#define NH 8
#define PH 16
#define DH 128
#define D0 56
#define NC 7
#define NL 3

// packed fp32x2 FMA (sm_103a): acc += h * w (2 lanes)
#define FFMA2(acc, h, w) \
    asm("fma.rn.f32x2 %0, %1, %2, %0;" : "+l"(acc) : "l"(h), "l"(w))
#define PACKW(dst, f) \
    asm("mov.b64 %0, {%1, %1};" : "=l"(dst) : "r"(__float_as_uint(f)))
#define UNPK(lo, hi, v) \
    do { unsigned int _a, _b; \
         asm("mov.b64 {%0,%1}, %2;" : "=r"(_a), "=r"(_b) : "l"(v)); \
         lo = __uint_as_float(_a); hi = __uint_as_float(_b); } while (0)

// ---------------- scratch (device globals; no allocation) ----------------
__device__ int   g_deg[NN];
__device__ int   g_off[NN + 1];
__device__ int   g_cur[NN];
__device__ int   g_srcs[ENT];
__device__ float g_norm[ENT];
__device__ float g_dinv[NN];
__device__ float g_hB[NN * D0];    // 56-dim node features
__device__ float g_hA[NN * PH];    // 16-dim node features (GAT output)
__device__ float g_agg[NN * D0];   // aggregated pre-GEMM features
__device__ float g_x1[NN * D0];    // XW0 (GNFE transform, stride 56)
__device__ float g_x2[NN * DH];    // hh = gcn_out @ gat_w
__device__ float g_es[NN * NH];
__device__ float g_ed[NN * NH];

// ---------------- CSR construction ----------------
__global__ void k_deg_init() {
    int i = blockIdx.x * blockDim.x + threadIdx.x;
    if (i < NN) g_deg[i] = 1;  // self-loop
}

__global__ void k_deg_count(const int* __restrict__ ei) {
    int e = blockIdx.x * blockDim.x + threadIdx.x;
    if (e < EE) atomicAdd(&g_deg[ei[EE + e]], 1);
}

__global__ void k_scan() {  // 1 block, 1024 threads
    __shared__ int ssum[1024];
    int tid = threadIdx.x;
    const int chunk = (NN + 1023) / 1024;
    int base = tid * chunk;
    int s = 0;
    for (int i = 0; i < chunk; i++) {
        int idx = base + i;
        if (idx < NN) s += g_deg[idx];
    }
    ssum[tid] = s;
    __syncthreads();
    for (int off = 1; off < 1024; off <<= 1) {
        int v = (tid >= off) ? ssum[tid - off] : 0;
        __syncthreads();
        ssum[tid] += v;
        __syncthreads();
    }
    if (tid == 0) g_off[NN] = ssum[1023];
    int run = tid ? ssum[tid - 1] : 0;
    for (int i = 0; i < chunk; i++) {
        int idx = base + i;
        if (idx < NN) {
            g_off[idx] = run;
            g_cur[idx] = run;
            g_dinv[idx] = rsqrtf((float)g_deg[idx]);
            run += g_deg[idx];
        }
    }
}

__global__ void k_fill(const int* __restrict__ ei) {
    int e = blockIdx.x * blockDim.x + threadIdx.x;
    if (e >= ENT) return;
    int s, d;
    if (e < EE) { s = ei[e]; d = ei[EE + e]; }
    else        { s = d = e - EE; }
    int p = atomicAdd(&g_cur[d], 1);
    g_srcs[p] = s;
    g_norm[p] = g_dinv[s] * g_dinv[d];
}

// ---------------- GEMM0: x[N,1433] @ w_feat[1433,56] -> g_x1 (stride 56) -------
// 64 rows x 56 cols per block; f32x2 packed accumulators (16 rows/thread).
#define XS_STRIDE 68
__global__ void k_gemm0(const float* __restrict__ x, const float* __restrict__ w) {
    __shared__ __align__(16) float xs_t[16 * XS_STRIDE];   // [kk][row], padded
    __shared__ float ws[16 * 56];                          // [kk][col]
    int tx = threadIdx.x;             // 0..55 (col)
    int ty = threadIdx.y;             // 0..3  (row group of 16)
    int tid = ty * 56 + tx;           // 0..223
    int row0 = blockIdx.x * 64;
    unsigned long long acc2[8];
#pragma unroll
    for (int p = 0; p < 8; p++) acc2[p] = 0ull;
    for (int kt = 0; kt < 1433; kt += 16) {
        for (int i = tid; i < 64 * 16; i += 224) {
            int r = i >> 4, kk = i & 15;
            int gk = kt + kk, gr = row0 + r;
            xs_t[kk * XS_STRIDE + r] =
                (gk < 1433 && gr < NN) ? x[(int64_t)gr * 1433 + gk] : 0.f;
        }
        for (int i = tid; i < 16 * 56; i += 224) {
            int kk = i / 56, c = i - kk * 56;
            int gk = kt + kk;
            ws[i] = (gk < 1433) ? w[gk * 56 + c] : 0.f;
        }
        __syncthreads();
#pragma unroll
        for (int kk = 0; kk < 16; kk++) {
            const ulonglong2* hp =
                reinterpret_cast<const ulonglong2*>(&xs_t[kk * XS_STRIDE + ty * 16]);
            ulonglong2 v0 = hp[0], v1 = hp[1], v2 = hp[2], v3 = hp[3];
            unsigned long long w2;
            PACKW(w2, ws[kk * 56 + tx]);
            FFMA2(acc2[0], v0.x, w2); FFMA2(acc2[1], v0.y, w2);
            FFMA2(acc2[2], v1.x, w2); FFMA2(acc2[3], v1.y, w2);
            FFMA2(acc2[4], v2.x, w2); FFMA2(acc2[5], v2.y, w2);
            FFMA2(acc2[6], v3.x, w2); FFMA2(acc2[7], v3.y, w2);
        }
        __syncthreads();
    }
#pragma unroll
    for (int p = 0; p < 8; p++) {
        float lo, hi;
        UNPK(lo, hi, acc2[p]);
        int gr = row0 + ty * 16 + 2 * p;
        if (gr < NN)     g_x1[gr * 56 + tx] = lo;
        if (gr + 1 < NN) g_x1[(gr + 1) * 56 + tx] = hi;
    }
}

// ---------------- GCN aggregation: out[d,:] = sum_e norm * in[src,:]  (warp/dst) --
__global__ void k_agg(const float* __restrict__ in, int din, float* __restrict__ out,
                      const float* __restrict__ bias, int do_relu) {
    int w = (blockIdx.x * blockDim.x + threadIdx.x) >> 5;
    int lane = threadIdx.x & 31;
    if (w >= NN) return;
    int e0 = g_off[w], e1 = g_off[w + 1];
    int c1 = lane + 32;
    float a0 = 0.f, a1 = 0.f;
    for (int e = e0; e < e1; e++) {
        int s = g_srcs[e];
        float nm = g_norm[e];
        const float* rp = in + s * din;
        if (lane < din) a0 += nm * rp[lane];
        if (c1 < din)   a1 += nm * rp[c1];
    }
    if (lane < din) {
        float v = a0 + (bias ? bias[lane] : 0.f);
        if (do_relu) v = fmaxf(v, 0.f);
        out[w * din + lane] = v;
    }
    if (c1 < din) {
        float v = a1 + (bias ? bias[c1] : 0.f);
        if (do_relu) v = fmaxf(v, 0.f);
        out[w * din + c1] = v;
    }
}

// ---------------- fused GCN-GEMM (+bias,relu) then GAT-GEMM (+es/ed epilogue) ----
// 16 nodes per block, 128 threads (1 col each), f32x2 accumulators.
#define HT_STRIDE 20
__global__ void k_fused(const float* __restrict__ agg, int din,
                        const float* __restrict__ Wg, const float* __restrict__ bg,
                        const float* __restrict__ Wt,
                        const float* __restrict__ asrc, const float* __restrict__ adst) {
    __shared__ __align__(16) float as_t[D0 * 16];        // [k][row]
    __shared__ __align__(16) float h_t[DH * HT_STRIDE];  // [k][row], padded
    int j = threadIdx.x;
    int n0 = blockIdx.x * 16;
    for (int i = j; i < 16 * din; i += 128) {
        int r = i / din, k = i - r * din;
        as_t[k * 16 + r] = agg[(n0 + r) * din + k];
    }
    __syncthreads();

    unsigned long long acc2[8];
    {
        unsigned long long b2;
        PACKW(b2, bg[j]);
#pragma unroll
        for (int p = 0; p < 8; p++) acc2[p] = b2;
    }
    for (int k = 0; k < din; k++) {
        const ulonglong2* hp = reinterpret_cast<const ulonglong2*>(&as_t[k * 16]);
        ulonglong2 v0 = hp[0], v1 = hp[1], v2 = hp[2], v3 = hp[3];
        unsigned long long w2;
        PACKW(w2, Wg[k * 128 + j]);
        FFMA2(acc2[0], v0.x, w2); FFMA2(acc2[1], v0.y, w2);
        FFMA2(acc2[2], v1.x, w2); FFMA2(acc2[3], v1.y, w2);
        FFMA2(acc2[4], v2.x, w2); FFMA2(acc2[5], v2.y, w2);
        FFMA2(acc2[6], v3.x, w2); FFMA2(acc2[7], v3.y, w2);
    }
    // relu -> transposed smem for second GEMM
#pragma unroll
    for (int p = 0; p < 8; p++) {
        float lo, hi;
        UNPK(lo, hi, acc2[p]);
        h_t[j * HT_STRIDE + 2 * p]     = fmaxf(lo, 0.f);
        h_t[j * HT_STRIDE + 2 * p + 1] = fmaxf(hi, 0.f);
    }
    __syncthreads();

    // GEMM2: hh = h @ Wt
#pragma unroll
    for (int p = 0; p < 8; p++) acc2[p] = 0ull;
    for (int k = 0; k < 128; k++) {
        const ulonglong2* hp = reinterpret_cast<const ulonglong2*>(&h_t[k * HT_STRIDE]);
        ulonglong2 v0 = hp[0], v1 = hp[1], v2 = hp[2], v3 = hp[3];
        unsigned long long w2;
        PACKW(w2, Wt[k * 128 + j]);
        FFMA2(acc2[0], v0.x, w2); FFMA2(acc2[1], v0.y, w2);
        FFMA2(acc2[2], v1.x, w2); FFMA2(acc2[3], v1.y, w2);
        FFMA2(acc2[4], v2.x, w2); FFMA2(acc2[5], v2.y, w2);
        FFMA2(acc2[6], v3.x, w2); FFMA2(acc2[7], v3.y, w2);
    }
    float hh[16];
#pragma unroll
    for (int p = 0; p < 8; p++) UNPK(hh[2 * p], hh[2 * p + 1], acc2[p]);

    float av = asrc[j], dv = adst[j];
    int head = j >> 4;
#pragma unroll
    for (int r = 0; r < 16; r++) {
        g_x2[(n0 + r) * 128 + j] = hh[r];
        float vs = hh[r] * av;
        float vd = hh[r] * dv;
#pragma unroll
        for (int off = 8; off > 0; off >>= 1) {
            vs += __shfl_xor_sync(0xffffffffu, vs, off);
            vd += __shfl_xor_sync(0xffffffffu, vd, off);
        }
        if ((j & 15) == 0) {
            g_es[(n0 + r) * NH + head] = vs;
            g_ed[(n0 + r) * NH + head] = vd;
        }
    }
}

// ---------------- single-pass GAT edge aggregation (warp/dst) ----------------
// out = sum_e exp(e) * hh_src / sum_e exp(e), per head; then mean heads + bias.
__global__ void k_gat_edge(const float* __restrict__ gb) {
    int w = (blockIdx.x * blockDim.x + threadIdx.x) >> 5;
    int lane = threadIdx.x & 31;
    if (w >= NN) return;
    float edh = (lane < 8) ? g_ed[w * NH + lane] : 0.f;
    int e0 = g_off[w], e1 = g_off[w + 1];
    float a0 = 0.f, a1 = 0.f, a2 = 0.f, a3 = 0.f, dsum = 0.f;
    int h0 = lane >> 4;  // 0 or 1
    for (int e = e0; e < e1; e++) {
        int s = g_srcs[e];
        float wv = 0.f;
        if (lane < 8) {
            float v = g_es[s * NH + lane] + edh;
            v = v > 0.f ? v : 0.2f * v;
            wv = __expf(v);
            dsum += wv;
        }
        const float* hp = g_x2 + s * 128;
        float w0 = __shfl_sync(0xffffffffu, wv, h0);
        float w1 = __shfl_sync(0xffffffffu, wv, h0 + 2);
        float w2 = __shfl_sync(0xffffffffu, wv, h0 + 4);
        float w3 = __shfl_sync(0xffffffffu, wv, h0 + 6);
        a0 += w0 * hp[lane];
        a1 += w1 * hp[lane + 32];
        a2 += w2 * hp[lane + 64];
        a3 += w3 * hp[lane + 96];
    }
    float d0 = __shfl_sync(0xffffffffu, dsum, h0);
    float d1 = __shfl_sync(0xffffffffu, dsum, h0 + 2);
    float d2 = __shfl_sync(0xffffffffu, dsum, h0 + 4);
    float d3 = __shfl_sync(0xffffffffu, dsum, h0 + 6);
    float s4 = a0 / d0 + a1 / d1 + a2 / d2 + a3 / d3;
    s4 += __shfl_xor_sync(0xffffffffu, s4, 16);
    if (lane < 16) g_hA[w * PH + lane] = s4 * 0.125f + gb[lane];
}

// ---------------- MAS: g_hB = g_hA @ mas_w[16,56] + mas_b ----------------
__global__ void k_mas(const float* __restrict__ W, const float* __restrict__ b) {
    __shared__ float hs[16];
    int n = blockIdx.x;
    int j = threadIdx.x;
    if (j < 16) hs[j] = g_hA[n * PH + j];
    __syncthreads();
    if (j < D0) {
        float acc = b[j];
#pragma unroll
        for (int k = 0; k < 16; k++) acc += hs[k] * W[k * D0 + j];
        g_hB[n * D0 + j] = acc;
    }
}

// ---------------- output: d_out = g_hB @ out_w[56,7] + out_b ----------------
__global__ void k_out(const float* __restrict__ W, const float* __restrict__ b,
                      float* __restrict__ out) {
    int t = blockIdx.x * blockDim.x + threadIdx.x;
    if (t >= NN * NC) return;
    int n = t / NC, c = t - n * NC;
    float acc = b[c];
    const float* hr = g_hB + n * D0;
#pragma unroll
    for (int k = 0; k < D0; k++) acc += hr[k] * W[k * NC + c];
    out[t] = acc;
}

// ---------------- launcher ----------------
extern "C" void kernel_launch(void* const* d_in, const int* in_sizes, int n_in,
                              void* d_out, int out_size) {
    const float* x      = (const float*)d_in[0];
    const int*   ei     = (const int*)d_in[1];
    const float* w_feat = (const float*)d_in[2];
    const float* b_feat = (const float*)d_in[3];
    const float* gcn0_w = (const float*)d_in[4];
    const float* gcn0_b = (const float*)d_in[5];
    const float* gcn_w  = (const float*)d_in[6];
    const float* gcn_b  = (const float*)d_in[7];
    const float* gat_w  = (const float*)d_in[8];
    const float* gat_as = (const float*)d_in[9];
    const float* gat_ad = (const float*)d_in[10];
    const float* gat_b  = (const float*)d_in[11];
    const float* mas_w  = (const float*)d_in[12];
    const float* mas_b  = (const float*)d_in[13];
    const float* out_w  = (const float*)d_in[14];
    const float* out_b  = (const float*)d_in[15];
    float* out = (float*)d_out;
    (void)in_sizes; (void)n_in; (void)out_size;

    float *p_x1, *p_hA, *p_hB, *p_agg;
    cudaGetSymbolAddress((void**)&p_x1, g_x1);
    cudaGetSymbolAddress((void**)&p_hA, g_hA);
    cudaGetSymbolAddress((void**)&p_hB, g_hB);
    cudaGetSymbolAddress((void**)&p_agg, g_agg);

    // CSR build
    k_deg_init<<<(NN + 255) / 256, 256>>>();
    k_deg_count<<<(EE + 255) / 256, 256>>>(ei);
    k_scan<<<1, 1024>>>();
    k_fill<<<(ENT + 255) / 256, 256>>>(ei);

    // GNFE: transform (1433->56) then aggregate (+bias, relu)
    k_gemm0<<<(NN + 63) / 64, dim3(56, 4)>>>(x, w_feat);
    k_agg<<<NN / 8, 256>>>(p_x1, D0, p_hB, b_feat, 1);

    for (int m = 0; m < NL; m++) {
        for (int i = 0; i < NL; i++) {
            int din = i ? PH : D0;
            const float* hin = i ? p_hA : p_hB;
            const float* Wg = i ? (gcn_w + (m * (NL - 1) + (i - 1)) * PH * DH)
                                : (gcn0_w + m * D0 * DH);
            const float* bg = i ? (gcn_b + (m * (NL - 1) + (i - 1)) * DH)
                                : (gcn0_b + m * DH);
            int li = m * NL + i;
            // GCN: aggregate first (linear), then fused GEMM1+GEMM2
            k_agg<<<NN / 8, 256>>>(hin, din, p_agg, (const float*)0, 0);
            k_fused<<<NN / 16, 128>>>(p_agg, din, Wg, bg,
                                      gat_w + li * DH * DH,
                                      gat_as + li * NH * PH, gat_ad + li * NH * PH);
            // GAT: single-pass softmax aggregation
            k_gat_edge<<<NN / 8, 256>>>(gat_b + li * PH);
        }
        k_mas<<<NN, 64>>>(mas_w + m * PH * D0, mas_b + m * D0);
    }
    k_out<<<(NN * NC + 255) / 256, 256>>>(out_w, out_b, out);
}

// round 3
// speedup vs baseline: 1.2870x; 1.1125x over previous
#include <cuda_runtime.h>
#include <math.h>
#include <stdint.h>

#define NN 50000
#define NPAD 50016
#define EE 800000
#define ENT (EE + NN)
#define NH 8
#define PH 16
#define DH 128
#define D0 56
#define NC 7
#define NL 3
#define NB_SCAN 196  // ceil(50000/256)

// packed fp32x2 FMA (sm_103a)
#define FFMA2(acc, h, w) \
    asm("fma.rn.f32x2 %0, %1, %2, %0;" : "+l"(acc) : "l"(h), "l"(w))
#define PACKW(dst, f) \
    asm("mov.b64 %0, {%1, %1};" : "=l"(dst) : "r"(__float_as_uint(f)))
#define UNPK(lo, hi, v) \
    do { unsigned int _a, _b; \
         asm("mov.b64 {%0,%1}, %2;" : "=r"(_a), "=r"(_b) : "l"(v)); \
         lo = __uint_as_float(_a); hi = __uint_as_float(_b); } while (0)

// ---------------- scratch ----------------
__device__ int   g_deg[NN];
__device__ int   g_off[NN + 1];
__device__ int   g_cur[NN];
__device__ int   g_part[256];
__device__ int   g_partoff[256];
__device__ int   g_srcs[ENT];
__device__ float g_norm[ENT];
__device__ float g_dinv[NN];
__device__ float g_nsum[NPAD];
__device__ float g_hB[NPAD * D0];
__device__ float g_hA[NPAD * PH];
__device__ float g_agg[NPAD * D0];
__device__ float g_x1[NPAD * D0];
__device__ float g_x2[NPAD * DH];
__device__ float g_es[NPAD * NH];
__device__ float g_ed[NPAD * NH];
__device__ float g_wf[PH * DH];
__device__ float g_bvec[DH];
__device__ float g_fw[PH * NC];
__device__ float g_fb[NC];

// ---------------- CSR construction ----------------
__global__ void k_deg_init() {
    int i = blockIdx.x * blockDim.x + threadIdx.x;
    if (i < NN) g_deg[i] = 1;  // self-loop
    if (i < NPAD) g_nsum[i] = 0.f;
}

__global__ void k_deg_count(const int* __restrict__ ei) {
    int e = blockIdx.x * blockDim.x + threadIdx.x;
    if (e < EE) atomicAdd(&g_deg[ei[EE + e]], 1);
}

__global__ void k_scan1() {
    __shared__ int sh[256];
    int t = threadIdx.x;
    int i = blockIdx.x * 256 + t;
    int d = (i < NN) ? g_deg[i] : 0;
    sh[t] = d;
    __syncthreads();
#pragma unroll
    for (int off = 1; off < 256; off <<= 1) {
        int v = (t >= off) ? sh[t - off] : 0;
        __syncthreads();
        sh[t] += v;
        __syncthreads();
    }
    if (t == 255) g_part[blockIdx.x] = sh[255];
    if (i < NN) g_off[i] = sh[t] - d;  // exclusive within block
}

__global__ void k_scan2() {
    __shared__ int sh[256];
    int t = threadIdx.x;
    int v = (t < NB_SCAN) ? g_part[t] : 0;
    sh[t] = v;
    __syncthreads();
#pragma unroll
    for (int off = 1; off < 256; off <<= 1) {
        int u = (t >= off) ? sh[t - off] : 0;
        __syncthreads();
        sh[t] += u;
        __syncthreads();
    }
    g_partoff[t] = sh[t] - v;  // exclusive
}

__global__ void k_scan3() {
    int i = blockIdx.x * blockDim.x + threadIdx.x;
    if (i >= NN) return;
    int off = g_off[i] + g_partoff[i >> 8];
    g_off[i] = off;
    g_cur[i] = off;
    g_dinv[i] = rsqrtf((float)g_deg[i]);
    if (i == 0) g_off[NN] = ENT;
}

__global__ void k_fill(const int* __restrict__ ei) {
    int e = blockIdx.x * blockDim.x + threadIdx.x;
    if (e >= ENT) return;
    int s, d;
    if (e < EE) { s = ei[e]; d = ei[EE + e]; }
    else        { s = d = e - EE; }
    int p = atomicAdd(&g_cur[d], 1);
    float nm = g_dinv[s] * g_dinv[d];
    g_srcs[p] = s;
    g_norm[p] = nm;
    atomicAdd(&g_nsum[d], nm);
}

// ---------------- GEMM0: x[N,1433] @ w_feat[1433,56] -> g_x1 ----------------
#define XS_STRIDE 68
__global__ void k_gemm0(const float* __restrict__ x, const float* __restrict__ w) {
    __shared__ __align__(16) float xs_t[16 * XS_STRIDE];
    __shared__ float ws[16 * 56];
    int tx = threadIdx.x;
    int ty = threadIdx.y;
    int tid = ty * 56 + tx;
    int row0 = blockIdx.x * 64;
    unsigned long long acc2[8];
#pragma unroll
    for (int p = 0; p < 8; p++) acc2[p] = 0ull;
    for (int kt = 0; kt < 1433; kt += 16) {
        for (int i = tid; i < 64 * 16; i += 224) {
            int r = i >> 4, kk = i & 15;
            int gk = kt + kk, gr = row0 + r;
            xs_t[kk * XS_STRIDE + r] =
                (gk < 1433 && gr < NN) ? x[(int64_t)gr * 1433 + gk] : 0.f;
        }
        for (int i = tid; i < 16 * 56; i += 224) {
            int kk = i / 56, c = i - kk * 56;
            int gk = kt + kk;
            ws[i] = (gk < 1433) ? w[gk * 56 + c] : 0.f;
        }
        __syncthreads();
#pragma unroll
        for (int kk = 0; kk < 16; kk++) {
            const ulonglong2* hp =
                reinterpret_cast<const ulonglong2*>(&xs_t[kk * XS_STRIDE + ty * 16]);
            ulonglong2 v0 = hp[0], v1 = hp[1], v2 = hp[2], v3 = hp[3];
            unsigned long long w2;
            PACKW(w2, ws[kk * 56 + tx]);
            FFMA2(acc2[0], v0.x, w2); FFMA2(acc2[1], v0.y, w2);
            FFMA2(acc2[2], v1.x, w2); FFMA2(acc2[3], v1.y, w2);
            FFMA2(acc2[4], v2.x, w2); FFMA2(acc2[5], v2.y, w2);
            FFMA2(acc2[6], v3.x, w2); FFMA2(acc2[7], v3.y, w2);
        }
        __syncthreads();
    }
#pragma unroll
    for (int p = 0; p < 8; p++) {
        float lo, hi;
        UNPK(lo, hi, acc2[p]);
        int gr = row0 + ty * 16 + 2 * p;
        if (gr < NN)     g_x1[gr * 56 + tx] = lo;
        if (gr + 1 < NN) g_x1[(gr + 1) * 56 + tx] = hi;
    }
}

// ---------------- 56-dim aggregation (warp/dst, unroll 2) ----------------
__global__ void k_agg56(const float* __restrict__ in, float* __restrict__ out,
                        const float* __restrict__ bias, int do_relu) {
    int w = (blockIdx.x * blockDim.x + threadIdx.x) >> 5;
    int lane = threadIdx.x & 31;
    if (w >= NPAD) return;
    int c1 = lane + 32;
    float a0 = 0.f, a1 = 0.f;
    if (w < NN) {
        int e0 = g_off[w], e1 = g_off[w + 1];
        int e = e0;
        for (; e + 2 <= e1; e += 2) {
            int s0 = g_srcs[e], s1 = g_srcs[e + 1];
            float m0 = g_norm[e], m1 = g_norm[e + 1];
            const float* r0 = in + s0 * 56;
            const float* r1 = in + s1 * 56;
            a0 += m0 * r0[lane] + m1 * r1[lane];
            if (c1 < 56) a1 += m0 * r0[c1] + m1 * r1[c1];
        }
        if (e < e1) {
            int s0 = g_srcs[e];
            float m0 = g_norm[e];
            const float* r0 = in + s0 * 56;
            a0 += m0 * r0[lane];
            if (c1 < 56) a1 += m0 * r0[c1];
        }
    }
    float b0 = bias ? bias[lane] : 0.f;
    float v0 = a0 + b0;
    if (do_relu) v0 = fmaxf(v0, 0.f);
    out[w * 56 + lane] = v0;
    if (c1 < 56) {
        float b1 = bias ? bias[c1] : 0.f;
        float v1 = a1 + b1;
        if (do_relu) v1 = fmaxf(v1, 0.f);
        out[w * 56 + c1] = v1;
    }
}

// ---------------- 16-dim aggregation (2 dst per warp, unroll 2) ----------------
__global__ void k_agg16(const float* __restrict__ in, float* __restrict__ out) {
    int gw = (blockIdx.x * blockDim.x + threadIdx.x) >> 5;
    int lane = threadIdx.x & 31;
    int dst = gw * 2 + (lane >> 4);
    int hl = lane & 15;
    if (dst >= NPAD) return;
    float a = 0.f;
    if (dst < NN) {
        int e0 = g_off[dst], e1 = g_off[dst + 1];
        int e = e0;
        for (; e + 2 <= e1; e += 2) {
            int s0 = g_srcs[e], s1 = g_srcs[e + 1];
            float m0 = g_norm[e], m1 = g_norm[e + 1];
            a += m0 * in[s0 * 16 + hl] + m1 * in[s1 * 16 + hl];
        }
        if (e < e1) a += g_norm[e] * in[g_srcs[e] * 16 + hl];
    }
    out[dst * 16 + hl] = a;
}

// ---------------- fused GCN-GEMM (+bias,relu) + GAT-GEMM (+es/ed) ----------------
// 32 nodes/block, 128 threads (1 out-col each), f32x2 accumulators.
#define HT_STRIDE 36
template <int DIN>
__global__ void k_fused(const float* __restrict__ agg,
                        const float* __restrict__ Wg, const float* __restrict__ bg,
                        const float* __restrict__ bvec,
                        const float* __restrict__ Wt,
                        const float* __restrict__ asrc, const float* __restrict__ adst) {
    __shared__ __align__(16) float as_t[DIN * 32];
    __shared__ __align__(16) float h_t[DH * HT_STRIDE];
    __shared__ float ns[32];
    int j = threadIdx.x;
    int n0 = blockIdx.x * 32;
    for (int i = j; i < 32 * DIN; i += 128) {
        int r = i / DIN, k = i - r * DIN;
        as_t[k * 32 + r] = agg[(n0 + r) * DIN + k];
    }
    if (bvec && j < 32) ns[j] = g_nsum[n0 + j];
    __syncthreads();

    unsigned long long acc2[16];
#pragma unroll
    for (int p = 0; p < 16; p++) acc2[p] = 0ull;
#pragma unroll 2
    for (int k = 0; k < DIN; k++) {
        const ulonglong2* hp = reinterpret_cast<const ulonglong2*>(&as_t[k * 32]);
        unsigned long long w2;
        PACKW(w2, Wg[k * 128 + j]);
        ulonglong2 v0 = hp[0], v1 = hp[1], v2 = hp[2], v3 = hp[3];
        FFMA2(acc2[0], v0.x, w2); FFMA2(acc2[1], v0.y, w2);
        FFMA2(acc2[2], v1.x, w2); FFMA2(acc2[3], v1.y, w2);
        FFMA2(acc2[4], v2.x, w2); FFMA2(acc2[5], v2.y, w2);
        FFMA2(acc2[6], v3.x, w2); FFMA2(acc2[7], v3.y, w2);
        ulonglong2 v4 = hp[4], v5 = hp[5], v6 = hp[6], v7 = hp[7];
        FFMA2(acc2[8],  v4.x, w2); FFMA2(acc2[9],  v4.y, w2);
        FFMA2(acc2[10], v5.x, w2); FFMA2(acc2[11], v5.y, w2);
        FFMA2(acc2[12], v6.x, w2); FFMA2(acc2[13], v6.y, w2);
        FFMA2(acc2[14], v7.x, w2); FFMA2(acc2[15], v7.y, w2);
    }
    {
        float bb = bg[j];
        float bvj = bvec ? bvec[j] : 0.f;
#pragma unroll
        for (int p = 0; p < 16; p++) {
            float lo, hi;
            UNPK(lo, hi, acc2[p]);
            int r = 2 * p;
            lo += bb + (bvec ? ns[r] * bvj : 0.f);
            hi += bb + (bvec ? ns[r + 1] * bvj : 0.f);
            h_t[j * HT_STRIDE + r]     = fmaxf(lo, 0.f);
            h_t[j * HT_STRIDE + r + 1] = fmaxf(hi, 0.f);
        }
    }
    __syncthreads();

#pragma unroll
    for (int p = 0; p < 16; p++) acc2[p] = 0ull;
#pragma unroll 2
    for (int k = 0; k < DH; k++) {
        const ulonglong2* hp = reinterpret_cast<const ulonglong2*>(&h_t[k * HT_STRIDE]);
        unsigned long long w2;
        PACKW(w2, Wt[k * 128 + j]);
        ulonglong2 v0 = hp[0], v1 = hp[1], v2 = hp[2], v3 = hp[3];
        FFMA2(acc2[0], v0.x, w2); FFMA2(acc2[1], v0.y, w2);
        FFMA2(acc2[2], v1.x, w2); FFMA2(acc2[3], v1.y, w2);
        FFMA2(acc2[4], v2.x, w2); FFMA2(acc2[5], v2.y, w2);
        FFMA2(acc2[6], v3.x, w2); FFMA2(acc2[7], v3.y, w2);
        ulonglong2 v4 = hp[4], v5 = hp[5], v6 = hp[6], v7 = hp[7];
        FFMA2(acc2[8],  v4.x, w2); FFMA2(acc2[9],  v4.y, w2);
        FFMA2(acc2[10], v5.x, w2); FFMA2(acc2[11], v5.y, w2);
        FFMA2(acc2[12], v6.x, w2); FFMA2(acc2[13], v6.y, w2);
        FFMA2(acc2[14], v7.x, w2); FFMA2(acc2[15], v7.y, w2);
    }
    float av = asrc[j], dv = adst[j];
    int head = j >> 4;
#pragma unroll
    for (int p = 0; p < 16; p++) {
        float lo, hi;
        UNPK(lo, hi, acc2[p]);
#pragma unroll
        for (int q = 0; q < 2; q++) {
            float h = q ? hi : lo;
            int r = n0 + 2 * p + q;
            g_x2[r * 128 + j] = h;
            float vs = h * av;
            float vd = h * dv;
#pragma unroll
            for (int off = 8; off > 0; off >>= 1) {
                vs += __shfl_xor_sync(0xffffffffu, vs, off);
                vd += __shfl_xor_sync(0xffffffffu, vd, off);
            }
            if ((j & 15) == 0) {
                g_es[r * NH + head] = vs;
                g_ed[r * NH + head] = vd;
            }
        }
    }
}

// ---------------- single-pass GAT edge aggregation (warp/dst, float4) ----------------
__global__ void k_gat_edge(const float* __restrict__ gb) {
    int w = (blockIdx.x * blockDim.x + threadIdx.x) >> 5;
    int lane = threadIdx.x & 31;
    if (w >= NN) return;
    float edh = (lane < 8) ? g_ed[w * NH + lane] : 0.f;
    int hsel = lane >> 2;  // head owning this lane's float4
    int e0 = g_off[w], e1 = g_off[w + 1];
    float4 acc = make_float4(0.f, 0.f, 0.f, 0.f);
    float dsum = 0.f;
    int e = e0;
    for (; e + 2 <= e1; e += 2) {
        int s0 = g_srcs[e], s1 = g_srcs[e + 1];
        float w0 = 0.f, w1 = 0.f;
        if (lane < 8) {
            float v0 = g_es[s0 * NH + lane] + edh;
            float v1 = g_es[s1 * NH + lane] + edh;
            v0 = v0 > 0.f ? v0 : 0.2f * v0;
            v1 = v1 > 0.f ? v1 : 0.2f * v1;
            w0 = __expf(v0);
            w1 = __expf(v1);
            dsum += w0 + w1;
        }
        float wb0 = __shfl_sync(0xffffffffu, w0, hsel);
        float wb1 = __shfl_sync(0xffffffffu, w1, hsel);
        float4 h0 = reinterpret_cast<const float4*>(g_x2 + s0 * 128)[lane];
        float4 h1 = reinterpret_cast<const float4*>(g_x2 + s1 * 128)[lane];
        acc.x += wb0 * h0.x + wb1 * h1.x;
        acc.y += wb0 * h0.y + wb1 * h1.y;
        acc.z += wb0 * h0.z + wb1 * h1.z;
        acc.w += wb0 * h0.w + wb1 * h1.w;
    }
    if (e < e1) {
        int s0 = g_srcs[e];
        float w0 = 0.f;
        if (lane < 8) {
            float v0 = g_es[s0 * NH + lane] + edh;
            v0 = v0 > 0.f ? v0 : 0.2f * v0;
            w0 = __expf(v0);
            dsum += w0;
        }
        float wb0 = __shfl_sync(0xffffffffu, w0, hsel);
        float4 h0 = reinterpret_cast<const float4*>(g_x2 + s0 * 128)[lane];
        acc.x += wb0 * h0.x;
        acc.y += wb0 * h0.y;
        acc.z += wb0 * h0.z;
        acc.w += wb0 * h0.w;
    }
    // normalize by per-head denom
    float db = __shfl_sync(0xffffffffu, dsum, hsel);
    float inv = 1.f / db;
    acc.x *= inv; acc.y *= inv; acc.z *= inv; acc.w *= inv;
    // reduce over heads (lanes differing in bits 2..4 share channel group)
#pragma unroll
    for (int off = 4; off <= 16; off <<= 1) {
        acc.x += __shfl_xor_sync(0xffffffffu, acc.x, off);
        acc.y += __shfl_xor_sync(0xffffffffu, acc.y, off);
        acc.z += __shfl_xor_sync(0xffffffffu, acc.z, off);
        acc.w += __shfl_xor_sync(0xffffffffu, acc.w, off);
    }
    if (lane < 4) {
        float4 gb4 = reinterpret_cast<const float4*>(gb)[lane];
        float4 r;
        r.x = acc.x * 0.125f + gb4.x;
        r.y = acc.y * 0.125f + gb4.y;
        r.z = acc.z * 0.125f + gb4.z;
        r.w = acc.w * 0.125f + gb4.w;
        reinterpret_cast<float4*>(g_hA + w * PH)[lane] = r;
    }
}

// ---------------- prep: g_wf = masW @ Wg [16x128], g_bvec = mas_b @ Wg ----------------
__global__ void k_prep(const float* __restrict__ masW, const float* __restrict__ mas_b,
                       const float* __restrict__ Wg) {
    __shared__ float mw[16 * 56];
    __shared__ float mb[56];
    int j = threadIdx.x;
    for (int i = j; i < 16 * 56; i += 128) mw[i] = masW[i];
    if (j < 56) mb[j] = mas_b[j];
    __syncthreads();
    float accw[16];
#pragma unroll
    for (int k = 0; k < 16; k++) accw[k] = 0.f;
    float accb = 0.f;
    for (int t = 0; t < 56; t++) {
        float wv = Wg[t * 128 + j];
        accb += mb[t] * wv;
#pragma unroll
        for (int k = 0; k < 16; k++) accw[k] += mw[k * 56 + t] * wv;
    }
#pragma unroll
    for (int k = 0; k < 16; k++) g_wf[k * 128 + j] = accw[k];
    g_bvec[j] = accb;
}

// ---------------- prep_out: g_fw = masW @ out_w [16x7], g_fb = mas_b@out_w + out_b --
__global__ void k_prep_out(const float* __restrict__ masW, const float* __restrict__ mas_b,
                           const float* __restrict__ out_w, const float* __restrict__ out_b) {
    int j = threadIdx.x;
    if (j >= NC) return;
    float fb = out_b[j];
    float fw[16];
#pragma unroll
    for (int k = 0; k < 16; k++) fw[k] = 0.f;
    for (int t = 0; t < 56; t++) {
        float wv = out_w[t * NC + j];
        fb += mas_b[t] * wv;
#pragma unroll
        for (int k = 0; k < 16; k++) fw[k] += masW[k * 56 + t] * wv;
    }
#pragma unroll
    for (int k = 0; k < 16; k++) g_fw[k * NC + j] = fw[k];
    g_fb[j] = fb;
}

// ---------------- fused MAS+output: out = hA @ g_fw + g_fb ----------------
__global__ void k_masout(float* __restrict__ out) {
    int t = blockIdx.x * blockDim.x + threadIdx.x;
    if (t >= NN * NC) return;
    int n = t / NC, c = t - n * NC;
    float acc = g_fb[c];
    const float* hr = g_hA + n * PH;
#pragma unroll
    for (int k = 0; k < 16; k++) acc += hr[k] * g_fw[k * NC + c];
    out[t] = acc;
}

// ---------------- launcher ----------------
extern "C" void kernel_launch(void* const* d_in, const int* in_sizes, int n_in,
                              void* d_out, int out_size) {
    const float* x      = (const float*)d_in[0];
    const int*   ei     = (const int*)d_in[1];
    const float* w_feat = (const float*)d_in[2];
    const float* b_feat = (const float*)d_in[3];
    const float* gcn0_w = (const float*)d_in[4];
    const float* gcn0_b = (const float*)d_in[5];
    const float* gcn_w  = (const float*)d_in[6];
    const float* gcn_b  = (const float*)d_in[7];
    const float* gat_w  = (const float*)d_in[8];
    const float* gat_as = (const float*)d_in[9];
    const float* gat_ad = (const float*)d_in[10];
    const float* gat_b  = (const float*)d_in[11];
    const float* mas_w  = (const float*)d_in[12];
    const float* mas_b  = (const float*)d_in[13];
    const float* out_w  = (const float*)d_in[14];
    const float* out_b  = (const float*)d_in[15];
    float* out = (float*)d_out;
    (void)in_sizes; (void)n_in; (void)out_size;

    float *p_x1, *p_hA, *p_hB, *p_agg, *p_wf, *p_bvec;
    cudaGetSymbolAddress((void**)&p_x1, g_x1);
    cudaGetSymbolAddress((void**)&p_hA, g_hA);
    cudaGetSymbolAddress((void**)&p_hB, g_hB);
    cudaGetSymbolAddress((void**)&p_agg, g_agg);
    cudaGetSymbolAddress((void**)&p_wf, g_wf);
    cudaGetSymbolAddress((void**)&p_bvec, g_bvec);

    // CSR build (gemm0 interleaved so ncu's fixed capture slot lands on it)
    k_deg_init<<<(NPAD + 255) / 256, 256>>>();
    k_deg_count<<<(EE + 255) / 256, 256>>>(ei);
    k_scan1<<<NB_SCAN, 256>>>();
    k_gemm0<<<(NN + 63) / 64, dim3(56, 4)>>>(x, w_feat);
    k_scan2<<<1, 256>>>();
    k_scan3<<<NB_SCAN, 256>>>();
    k_fill<<<(ENT + 255) / 256, 256>>>(ei);

    // GNFE: aggregate transformed features (+bias, relu)
    k_agg56<<<NPAD / 8, 256>>>(p_x1, p_hB, b_feat, 1);

    for (int m = 0; m < NL; m++) {
        for (int i = 0; i < NL; i++) {
            int li = m * NL + i;
            const float* Wt = gat_w + li * DH * DH;
            const float* as = gat_as + li * NH * PH;
            const float* ad = gat_ad + li * NH * PH;
            if (i == 0) {
                if (m == 0) {
                    k_agg56<<<NPAD / 8, 256>>>(p_hB, p_agg, (const float*)0, 0);
                    k_fused<D0><<<NPAD / 32, 128>>>(p_agg, gcn0_w, gcn0_b,
                                                    (const float*)0, Wt, as, ad);
                } else {
                    k_prep<<<1, 128>>>(mas_w + (m - 1) * PH * D0,
                                       mas_b + (m - 1) * D0,
                                       gcn0_w + m * D0 * DH);
                    k_agg16<<<NPAD / 16, 256>>>(p_hA, p_agg);
                    k_fused<PH><<<NPAD / 32, 128>>>(p_agg, p_wf, gcn0_b + m * DH,
                                                    p_bvec, Wt, as, ad);
                }
            } else {
                k_agg16<<<NPAD / 16, 256>>>(p_hA, p_agg);
                k_fused<PH><<<NPAD / 32, 128>>>(
                    p_agg, gcn_w + (m * (NL - 1) + (i - 1)) * PH * DH,
                    gcn_b + (m * (NL - 1) + (i - 1)) * DH,
                    (const float*)0, Wt, as, ad);
            }
            k_gat_edge<<<(NN * 32 + 255) / 256, 256>>>(gat_b + li * PH);
        }
    }
    k_prep_out<<<1, 32>>>(mas_w + 2 * PH * D0, mas_b + 2 * D0, out_w, out_b);
    k_masout<<<(NN * NC + 255) / 256, 256>>>(out);
}

// round 4
// speedup vs baseline: 1.6944x; 1.3165x over previous
#include <cuda_runtime.h>
#include <cuda_bf16.h>
#include <math.h>
#include <stdint.h>

#define NN 50000
#define NPAD 50016
#define EE 800000
#define ENT (EE + NN)
#define NH 8
#define PH 16
#define DH 128
#define D0 56
#define NC 7
#define NL 3
#define NB_SCAN 196  // ceil(50000/256)

// packed fp32x2 FMA (sm_103a)
#define FFMA2(acc, h, w) \
    asm("fma.rn.f32x2 %0, %1, %2, %0;" : "+l"(acc) : "l"(h), "l"(w))
#define PACKW(dst, f) \
    asm("mov.b64 %0, {%1, %1};" : "=l"(dst) : "r"(__float_as_uint(f)))
#define UNPK(lo, hi, v) \
    do { unsigned int _a, _b; \
         asm("mov.b64 {%0,%1}, %2;" : "=r"(_a), "=r"(_b) : "l"(v)); \
         lo = __uint_as_float(_a); hi = __uint_as_float(_b); } while (0)

// ---------------- scratch ----------------
__device__ int   g_deg[NN];
__device__ int   g_off[NN + 1];
__device__ int   g_cur[NN];
__device__ int   g_part[256];
__device__ int   g_partoff[256];
__device__ int   g_srcs[ENT];
__device__ float g_norm[ENT];
__device__ float g_dinv[NN];
__device__ float g_nsum[NPAD];
__device__ float g_hB[NPAD * D0];
__device__ float g_hA[NPAD * PH];
__device__ float g_agg[NPAD * D0];
__device__ float g_x1[NPAD * D0];
__device__ float g_x2[NPAD * DH];
__device__ float g_es[NPAD * NH];
__device__ float g_ed[NPAD * NH];
__device__ float g_wf[PH * DH];
__device__ float g_bvec[DH];
__device__ float g_fw[PH * NC];
__device__ float g_fb[NC];

// ---------------- CSR construction ----------------
__global__ void k_deg_init() {
    int i = blockIdx.x * blockDim.x + threadIdx.x;
    if (i < NN) g_deg[i] = 1;  // self-loop
    if (i < NPAD) g_nsum[i] = 0.f;
}

__global__ void k_deg_count(const int* __restrict__ ei) {
    int e = blockIdx.x * blockDim.x + threadIdx.x;
    if (e < EE) atomicAdd(&g_deg[ei[EE + e]], 1);
}

__global__ void k_scan1() {
    __shared__ int sh[256];
    int t = threadIdx.x;
    int i = blockIdx.x * 256 + t;
    int d = (i < NN) ? g_deg[i] : 0;
    sh[t] = d;
    __syncthreads();
#pragma unroll
    for (int off = 1; off < 256; off <<= 1) {
        int v = (t >= off) ? sh[t - off] : 0;
        __syncthreads();
        sh[t] += v;
        __syncthreads();
    }
    if (t == 255) g_part[blockIdx.x] = sh[255];
    if (i < NN) g_off[i] = sh[t] - d;
}

__global__ void k_scan2() {
    __shared__ int sh[256];
    int t = threadIdx.x;
    int v = (t < NB_SCAN) ? g_part[t] : 0;
    sh[t] = v;
    __syncthreads();
#pragma unroll
    for (int off = 1; off < 256; off <<= 1) {
        int u = (t >= off) ? sh[t - off] : 0;
        __syncthreads();
        sh[t] += u;
        __syncthreads();
    }
    g_partoff[t] = sh[t] - v;
}

__global__ void k_scan3() {
    int i = blockIdx.x * blockDim.x + threadIdx.x;
    if (i >= NN) return;
    int off = g_off[i] + g_partoff[i >> 8];
    g_off[i] = off;
    g_cur[i] = off;
    g_dinv[i] = rsqrtf((float)g_deg[i]);
    if (i == 0) g_off[NN] = ENT;
}

__global__ void k_fill(const int* __restrict__ ei) {
    int e = blockIdx.x * blockDim.x + threadIdx.x;
    if (e >= ENT) return;
    int s, d;
    if (e < EE) { s = ei[e]; d = ei[EE + e]; }
    else        { s = d = e - EE; }
    int p = atomicAdd(&g_cur[d], 1);
    float nm = g_dinv[s] * g_dinv[d];
    g_srcs[p] = s;
    g_norm[p] = nm;
    atomicAdd(&g_nsum[d], nm);
}

// ---------------- tensor-core GEMM0 (split-bf16 emulated fp32) ----------------
// x[N,1433] @ w[1433,56] -> g_x1 (stride 56).
// Block: 64 rows x 64 cols (padded from 56), BK=32, 256 threads (8 warps 2x4).
__device__ __forceinline__ void ldm_x4(uint32_t& r0, uint32_t& r1, uint32_t& r2,
                                       uint32_t& r3, uint32_t addr) {
    asm volatile("ldmatrix.sync.aligned.m8n8.x4.shared.b16 {%0,%1,%2,%3}, [%4];"
                 : "=r"(r0), "=r"(r1), "=r"(r2), "=r"(r3) : "r"(addr));
}
__device__ __forceinline__ void ldm_x2t(uint32_t& r0, uint32_t& r1, uint32_t addr) {
    asm volatile("ldmatrix.sync.aligned.m8n8.x2.trans.shared.b16 {%0,%1}, [%2];"
                 : "=r"(r0), "=r"(r1) : "r"(addr));
}
__device__ __forceinline__ void mma_bf16(float* c, const uint32_t* a, const uint32_t* b) {
    asm volatile(
        "mma.sync.aligned.m16n8k16.row.col.f32.bf16.bf16.f32 "
        "{%0,%1,%2,%3}, {%4,%5,%6,%7}, {%8,%9}, {%0,%1,%2,%3};"
        : "+f"(c[0]), "+f"(c[1]), "+f"(c[2]), "+f"(c[3])
        : "r"(a[0]), "r"(a[1]), "r"(a[2]), "r"(a[3]), "r"(b[0]), "r"(b[1]));
}

#define SA_STRIDE 40   // 64 rows x (32+8) bf16 : 80B row stride, ldmatrix conflict-free
#define SB_STRIDE 72   // 32 rows x (64+8) bf16 : 144B row stride, conflict-free

__global__ __launch_bounds__(256, 3)
void k_gemm0(const float* __restrict__ x, const float* __restrict__ w) {
    __shared__ __align__(16) __nv_bfloat16 sAh[64 * SA_STRIDE];
    __shared__ __align__(16) __nv_bfloat16 sAl[64 * SA_STRIDE];
    __shared__ __align__(16) __nv_bfloat16 sBh[32 * SB_STRIDE];
    __shared__ __align__(16) __nv_bfloat16 sBl[32 * SB_STRIDE];

    int tid = threadIdx.x;
    int lane = tid & 31;
    int wid = tid >> 5;
    int warp_m = wid >> 2;        // 0..1 -> 32 rows each
    int warp_n = wid & 3;         // 0..3 -> 16 cols each
    int row0 = blockIdx.x * 64;

    // A load mapping: r = tid/4 (0..63), 8 consecutive k per thread
    int a_r = tid >> 2;
    int a_c0 = (tid & 3) * 8;
    // B load mapping: k = tid/8 (0..31), 8 consecutive n per thread
    int b_k = tid >> 3;
    int b_n0 = (tid & 7) * 8;

    // ldmatrix shared addresses (fixed per thread)
    uint32_t baseAh = (uint32_t)__cvta_generic_to_shared(sAh);
    uint32_t baseAl = (uint32_t)__cvta_generic_to_shared(sAl);
    uint32_t baseBh = (uint32_t)__cvta_generic_to_shared(sBh);
    uint32_t baseBl = (uint32_t)__cvta_generic_to_shared(sBl);

    float acc[2][2][4];
#pragma unroll
    for (int mt = 0; mt < 2; mt++)
#pragma unroll
        for (int nt = 0; nt < 2; nt++)
#pragma unroll
            for (int q = 0; q < 4; q++) acc[mt][nt][q] = 0.f;

    for (int it = 0; it < 45; it++) {
        int k0g = it * 32;
        // ---- load + split-convert A tile (64x32) ----
        {
            int gr = row0 + a_r;
            const float* xp = x + (int64_t)gr * 1433 + k0g + a_c0;
            __nv_bfloat16* ph = &sAh[a_r * SA_STRIDE + a_c0];
            __nv_bfloat16* pl = &sAl[a_r * SA_STRIDE + a_c0];
#pragma unroll
            for (int i = 0; i < 8; i++) {
                int gk = k0g + a_c0 + i;
                float v = (gr < NN && gk < 1433) ? xp[i] : 0.f;
                __nv_bfloat16 hi = __float2bfloat16(v);
                ph[i] = hi;
                pl[i] = __float2bfloat16(v - __bfloat162float(hi));
            }
        }
        // ---- load + split-convert B tile (32x64, n padded) ----
        {
            int gk = k0g + b_k;
            const float* wp = w + (int64_t)gk * 56 + b_n0;
            __nv_bfloat16* ph = &sBh[b_k * SB_STRIDE + b_n0];
            __nv_bfloat16* pl = &sBl[b_k * SB_STRIDE + b_n0];
#pragma unroll
            for (int i = 0; i < 8; i++) {
                int n = b_n0 + i;
                float v = (gk < 1433 && n < 56) ? wp[i] : 0.f;
                __nv_bfloat16 hi = __float2bfloat16(v);
                ph[i] = hi;
                pl[i] = __float2bfloat16(v - __bfloat162float(hi));
            }
        }
        __syncthreads();

#pragma unroll
        for (int ks = 0; ks < 2; ks++) {
            int k0 = ks * 16;
            uint32_t ah[2][4], al[2][4], bh[2][2], bl[2][2];
            // A fragments: rows warp_m*32 + mt*16 + (lane&15), k half by lane>>4
            int arow_base = warp_m * 32 + (lane & 15);
            int acol = k0 + (lane >> 4) * 8;
#pragma unroll
            for (int mt = 0; mt < 2; mt++) {
                uint32_t off = ((arow_base + mt * 16) * SA_STRIDE + acol) * 2;
                ldm_x4(ah[mt][0], ah[mt][1], ah[mt][2], ah[mt][3], baseAh + off);
                ldm_x4(al[mt][0], al[mt][1], al[mt][2], al[mt][3], baseAl + off);
            }
            // B fragments: rows k0 + (lane&15), col warp_n*16 + nt*8
            int brow = k0 + (lane & 15);
#pragma unroll
            for (int nt = 0; nt < 2; nt++) {
                uint32_t off = (brow * SB_STRIDE + warp_n * 16 + nt * 8) * 2;
                ldm_x2t(bh[nt][0], bh[nt][1], baseBh + off);
                ldm_x2t(bl[nt][0], bl[nt][1], baseBl + off);
            }
#pragma unroll
            for (int mt = 0; mt < 2; mt++)
#pragma unroll
                for (int nt = 0; nt < 2; nt++) {
                    mma_bf16(acc[mt][nt], ah[mt], bh[nt]);
                    mma_bf16(acc[mt][nt], ah[mt], bl[nt]);
                    mma_bf16(acc[mt][nt], al[mt], bh[nt]);
                }
        }
        __syncthreads();
    }

    // ---- epilogue ----
#pragma unroll
    for (int mt = 0; mt < 2; mt++) {
        int rbase = row0 + warp_m * 32 + mt * 16 + (lane >> 2);
#pragma unroll
        for (int nt = 0; nt < 2; nt++) {
            int col = warp_n * 16 + nt * 8 + ((lane & 3) << 1);
            if (col + 1 < 56) {
                if (rbase < NN) {
                    g_x1[rbase * 56 + col]     = acc[mt][nt][0];
                    g_x1[rbase * 56 + col + 1] = acc[mt][nt][1];
                }
                if (rbase + 8 < NN) {
                    g_x1[(rbase + 8) * 56 + col]     = acc[mt][nt][2];
                    g_x1[(rbase + 8) * 56 + col + 1] = acc[mt][nt][3];
                }
            }
        }
    }
}

// ---------------- 56-dim aggregation (warp/dst, unroll 2) ----------------
__global__ void k_agg56(const float* __restrict__ in, float* __restrict__ out,
                        const float* __restrict__ bias, int do_relu) {
    int w = (blockIdx.x * blockDim.x + threadIdx.x) >> 5;
    int lane = threadIdx.x & 31;
    if (w >= NPAD) return;
    int c1 = lane + 32;
    float a0 = 0.f, a1 = 0.f;
    if (w < NN) {
        int e0 = g_off[w], e1 = g_off[w + 1];
        int e = e0;
        for (; e + 2 <= e1; e += 2) {
            int s0 = g_srcs[e], s1 = g_srcs[e + 1];
            float m0 = g_norm[e], m1 = g_norm[e + 1];
            const float* r0 = in + s0 * 56;
            const float* r1 = in + s1 * 56;
            a0 += m0 * r0[lane] + m1 * r1[lane];
            if (c1 < 56) a1 += m0 * r0[c1] + m1 * r1[c1];
        }
        if (e < e1) {
            int s0 = g_srcs[e];
            float m0 = g_norm[e];
            const float* r0 = in + s0 * 56;
            a0 += m0 * r0[lane];
            if (c1 < 56) a1 += m0 * r0[c1];
        }
    }
    float b0 = bias ? bias[lane] : 0.f;
    float v0 = a0 + b0;
    if (do_relu) v0 = fmaxf(v0, 0.f);
    out[w * 56 + lane] = v0;
    if (c1 < 56) {
        float b1 = bias ? bias[c1] : 0.f;
        float v1 = a1 + b1;
        if (do_relu) v1 = fmaxf(v1, 0.f);
        out[w * 56 + c1] = v1;
    }
}

// ---------------- 16-dim aggregation (2 dst per warp, unroll 2) ----------------
__global__ void k_agg16(const float* __restrict__ in, float* __restrict__ out) {
    int gw = (blockIdx.x * blockDim.x + threadIdx.x) >> 5;
    int lane = threadIdx.x & 31;
    int dst = gw * 2 + (lane >> 4);
    int hl = lane & 15;
    if (dst >= NPAD) return;
    float a = 0.f;
    if (dst < NN) {
        int e0 = g_off[dst], e1 = g_off[dst + 1];
        int e = e0;
        for (; e + 2 <= e1; e += 2) {
            int s0 = g_srcs[e], s1 = g_srcs[e + 1];
            float m0 = g_norm[e], m1 = g_norm[e + 1];
            a += m0 * in[s0 * 16 + hl] + m1 * in[s1 * 16 + hl];
        }
        if (e < e1) a += g_norm[e] * in[g_srcs[e] * 16 + hl];
    }
    out[dst * 16 + hl] = a;
}

// ---------------- fused GCN-GEMM (+bias,relu) + GAT-GEMM (+es/ed) ----------------
#define HT_STRIDE 36
template <int DIN>
__global__ void k_fused(const float* __restrict__ agg,
                        const float* __restrict__ Wg, const float* __restrict__ bg,
                        const float* __restrict__ bvec,
                        const float* __restrict__ Wt,
                        const float* __restrict__ asrc, const float* __restrict__ adst) {
    __shared__ __align__(16) float as_t[DIN * 32];
    __shared__ __align__(16) float h_t[DH * HT_STRIDE];
    __shared__ float ns[32];
    int j = threadIdx.x;
    int n0 = blockIdx.x * 32;
    for (int i = j; i < 32 * DIN; i += 128) {
        int r = i / DIN, k = i - r * DIN;
        as_t[k * 32 + r] = agg[(n0 + r) * DIN + k];
    }
    if (bvec && j < 32) ns[j] = g_nsum[n0 + j];
    __syncthreads();

    unsigned long long acc2[16];
#pragma unroll
    for (int p = 0; p < 16; p++) acc2[p] = 0ull;
#pragma unroll 2
    for (int k = 0; k < DIN; k++) {
        const ulonglong2* hp = reinterpret_cast<const ulonglong2*>(&as_t[k * 32]);
        unsigned long long w2;
        PACKW(w2, Wg[k * 128 + j]);
        ulonglong2 v0 = hp[0], v1 = hp[1], v2 = hp[2], v3 = hp[3];
        FFMA2(acc2[0], v0.x, w2); FFMA2(acc2[1], v0.y, w2);
        FFMA2(acc2[2], v1.x, w2); FFMA2(acc2[3], v1.y, w2);
        FFMA2(acc2[4], v2.x, w2); FFMA2(acc2[5], v2.y, w2);
        FFMA2(acc2[6], v3.x, w2); FFMA2(acc2[7], v3.y, w2);
        ulonglong2 v4 = hp[4], v5 = hp[5], v6 = hp[6], v7 = hp[7];
        FFMA2(acc2[8],  v4.x, w2); FFMA2(acc2[9],  v4.y, w2);
        FFMA2(acc2[10], v5.x, w2); FFMA2(acc2[11], v5.y, w2);
        FFMA2(acc2[12], v6.x, w2); FFMA2(acc2[13], v6.y, w2);
        FFMA2(acc2[14], v7.x, w2); FFMA2(acc2[15], v7.y, w2);
    }
    {
        float bb = bg[j];
        float bvj = bvec ? bvec[j] : 0.f;
#pragma unroll
        for (int p = 0; p < 16; p++) {
            float lo, hi;
            UNPK(lo, hi, acc2[p]);
            int r = 2 * p;
            lo += bb + (bvec ? ns[r] * bvj : 0.f);
            hi += bb + (bvec ? ns[r + 1] * bvj : 0.f);
            h_t[j * HT_STRIDE + r]     = fmaxf(lo, 0.f);
            h_t[j * HT_STRIDE + r + 1] = fmaxf(hi, 0.f);
        }
    }
    __syncthreads();

#pragma unroll
    for (int p = 0; p < 16; p++) acc2[p] = 0ull;
#pragma unroll 2
    for (int k = 0; k < DH; k++) {
        const ulonglong2* hp = reinterpret_cast<const ulonglong2*>(&h_t[k * HT_STRIDE]);
        unsigned long long w2;
        PACKW(w2, Wt[k * 128 + j]);
        ulonglong2 v0 = hp[0], v1 = hp[1], v2 = hp[2], v3 = hp[3];
        FFMA2(acc2[0], v0.x, w2); FFMA2(acc2[1], v0.y, w2);
        FFMA2(acc2[2], v1.x, w2); FFMA2(acc2[3], v1.y, w2);
        FFMA2(acc2[4], v2.x, w2); FFMA2(acc2[5], v2.y, w2);
        FFMA2(acc2[6], v3.x, w2); FFMA2(acc2[7], v3.y, w2);
        ulonglong2 v4 = hp[4], v5 = hp[5], v6 = hp[6], v7 = hp[7];
        FFMA2(acc2[8],  v4.x, w2); FFMA2(acc2[9],  v4.y, w2);
        FFMA2(acc2[10], v5.x, w2); FFMA2(acc2[11], v5.y, w2);
        FFMA2(acc2[12], v6.x, w2); FFMA2(acc2[13], v6.y, w2);
        FFMA2(acc2[14], v7.x, w2); FFMA2(acc2[15], v7.y, w2);
    }
    float av = asrc[j], dv = adst[j];
    int head = j >> 4;
#pragma unroll
    for (int p = 0; p < 16; p++) {
        float lo, hi;
        UNPK(lo, hi, acc2[p]);
#pragma unroll
        for (int q = 0; q < 2; q++) {
            float h = q ? hi : lo;
            int r = n0 + 2 * p + q;
            g_x2[r * 128 + j] = h;
            float vs = h * av;
            float vd = h * dv;
#pragma unroll
            for (int off = 8; off > 0; off >>= 1) {
                vs += __shfl_xor_sync(0xffffffffu, vs, off);
                vd += __shfl_xor_sync(0xffffffffu, vd, off);
            }
            if ((j & 15) == 0) {
                g_es[r * NH + head] = vs;
                g_ed[r * NH + head] = vd;
            }
        }
    }
}

// ---------------- single-pass GAT edge aggregation (warp/dst, float4) ----------------
__global__ void k_gat_edge(const float* __restrict__ gb) {
    int w = (blockIdx.x * blockDim.x + threadIdx.x) >> 5;
    int lane = threadIdx.x & 31;
    if (w >= NN) return;
    float edh = (lane < 8) ? g_ed[w * NH + lane] : 0.f;
    int hsel = lane >> 2;
    int e0 = g_off[w], e1 = g_off[w + 1];
    float4 acc = make_float4(0.f, 0.f, 0.f, 0.f);
    float dsum = 0.f;
    int e = e0;
    for (; e + 2 <= e1; e += 2) {
        int s0 = g_srcs[e], s1 = g_srcs[e + 1];
        float w0 = 0.f, w1 = 0.f;
        if (lane < 8) {
            float v0 = g_es[s0 * NH + lane] + edh;
            float v1 = g_es[s1 * NH + lane] + edh;
            v0 = v0 > 0.f ? v0 : 0.2f * v0;
            v1 = v1 > 0.f ? v1 : 0.2f * v1;
            w0 = __expf(v0);
            w1 = __expf(v1);
            dsum += w0 + w1;
        }
        float wb0 = __shfl_sync(0xffffffffu, w0, hsel);
        float wb1 = __shfl_sync(0xffffffffu, w1, hsel);
        float4 h0 = reinterpret_cast<const float4*>(g_x2 + s0 * 128)[lane];
        float4 h1 = reinterpret_cast<const float4*>(g_x2 + s1 * 128)[lane];
        acc.x += wb0 * h0.x + wb1 * h1.x;
        acc.y += wb0 * h0.y + wb1 * h1.y;
        acc.z += wb0 * h0.z + wb1 * h1.z;
        acc.w += wb0 * h0.w + wb1 * h1.w;
    }
    if (e < e1) {
        int s0 = g_srcs[e];
        float w0 = 0.f;
        if (lane < 8) {
            float v0 = g_es[s0 * NH + lane] + edh;
            v0 = v0 > 0.f ? v0 : 0.2f * v0;
            w0 = __expf(v0);
            dsum += w0;
        }
        float wb0 = __shfl_sync(0xffffffffu, w0, hsel);
        float4 h0 = reinterpret_cast<const float4*>(g_x2 + s0 * 128)[lane];
        acc.x += wb0 * h0.x;
        acc.y += wb0 * h0.y;
        acc.z += wb0 * h0.z;
        acc.w += wb0 * h0.w;
    }
    float db = __shfl_sync(0xffffffffu, dsum, hsel);
    float inv = 1.f / db;
    acc.x *= inv; acc.y *= inv; acc.z *= inv; acc.w *= inv;
#pragma unroll
    for (int off = 4; off <= 16; off <<= 1) {
        acc.x += __shfl_xor_sync(0xffffffffu, acc.x, off);
        acc.y += __shfl_xor_sync(0xffffffffu, acc.y, off);
        acc.z += __shfl_xor_sync(0xffffffffu, acc.z, off);
        acc.w += __shfl_xor_sync(0xffffffffu, acc.w, off);
    }
    if (lane < 4) {
        float4 gb4 = reinterpret_cast<const float4*>(gb)[lane];
        float4 r;
        r.x = acc.x * 0.125f + gb4.x;
        r.y = acc.y * 0.125f + gb4.y;
        r.z = acc.z * 0.125f + gb4.z;
        r.w = acc.w * 0.125f + gb4.w;
        reinterpret_cast<float4*>(g_hA + w * PH)[lane] = r;
    }
}

// ---------------- prep: g_wf = masW @ Wg [16x128], g_bvec = mas_b @ Wg ----------------
__global__ void k_prep(const float* __restrict__ masW, const float* __restrict__ mas_b,
                       const float* __restrict__ Wg) {
    __shared__ float mw[16 * 56];
    __shared__ float mb[56];
    int j = threadIdx.x;
    for (int i = j; i < 16 * 56; i += 128) mw[i] = masW[i];
    if (j < 56) mb[j] = mas_b[j];
    __syncthreads();
    float accw[16];
#pragma unroll
    for (int k = 0; k < 16; k++) accw[k] = 0.f;
    float accb = 0.f;
    for (int t = 0; t < 56; t++) {
        float wv = Wg[t * 128 + j];
        accb += mb[t] * wv;
#pragma unroll
        for (int k = 0; k < 16; k++) accw[k] += mw[k * 56 + t] * wv;
    }
#pragma unroll
    for (int k = 0; k < 16; k++) g_wf[k * 128 + j] = accw[k];
    g_bvec[j] = accb;
}

// ---------------- prep_out ----------------
__global__ void k_prep_out(const float* __restrict__ masW, const float* __restrict__ mas_b,
                           const float* __restrict__ out_w, const float* __restrict__ out_b) {
    int j = threadIdx.x;
    if (j >= NC) return;
    float fb = out_b[j];
    float fw[16];
#pragma unroll
    for (int k = 0; k < 16; k++) fw[k] = 0.f;
    for (int t = 0; t < 56; t++) {
        float wv = out_w[t * NC + j];
        fb += mas_b[t] * wv;
#pragma unroll
        for (int k = 0; k < 16; k++) fw[k] += masW[k * 56 + t] * wv;
    }
#pragma unroll
    for (int k = 0; k < 16; k++) g_fw[k * NC + j] = fw[k];
    g_fb[j] = fb;
}

// ---------------- fused MAS+output ----------------
__global__ void k_masout(float* __restrict__ out) {
    int t = blockIdx.x * blockDim.x + threadIdx.x;
    if (t >= NN * NC) return;
    int n = t / NC, c = t - n * NC;
    float acc = g_fb[c];
    const float* hr = g_hA + n * PH;
#pragma unroll
    for (int k = 0; k < 16; k++) acc += hr[k] * g_fw[k * NC + c];
    out[t] = acc;
}

// ---------------- launcher ----------------
extern "C" void kernel_launch(void* const* d_in, const int* in_sizes, int n_in,
                              void* d_out, int out_size) {
    const float* x      = (const float*)d_in[0];
    const int*   ei     = (const int*)d_in[1];
    const float* w_feat = (const float*)d_in[2];
    const float* b_feat = (const float*)d_in[3];
    const float* gcn0_w = (const float*)d_in[4];
    const float* gcn0_b = (const float*)d_in[5];
    const float* gcn_w  = (const float*)d_in[6];
    const float* gcn_b  = (const float*)d_in[7];
    const float* gat_w  = (const float*)d_in[8];
    const float* gat_as = (const float*)d_in[9];
    const float* gat_ad = (const float*)d_in[10];
    const float* gat_b  = (const float*)d_in[11];
    const float* mas_w  = (const float*)d_in[12];
    const float* mas_b  = (const float*)d_in[13];
    const float* out_w  = (const float*)d_in[14];
    const float* out_b  = (const float*)d_in[15];
    float* out = (float*)d_out;
    (void)in_sizes; (void)n_in; (void)out_size;

    float *p_x1, *p_hA, *p_hB, *p_agg, *p_wf, *p_bvec;
    cudaGetSymbolAddress((void**)&p_x1, g_x1);
    cudaGetSymbolAddress((void**)&p_hA, g_hA);
    cudaGetSymbolAddress((void**)&p_hB, g_hB);
    cudaGetSymbolAddress((void**)&p_agg, g_agg);
    cudaGetSymbolAddress((void**)&p_wf, g_wf);
    cudaGetSymbolAddress((void**)&p_bvec, g_bvec);

    // CSR build; gemm0 placed 6th so ncu (-s 5 -c 1) captures it
    k_deg_init<<<(NPAD + 255) / 256, 256>>>();
    k_deg_count<<<(EE + 255) / 256, 256>>>(ei);
    k_scan1<<<NB_SCAN, 256>>>();
    k_scan2<<<1, 256>>>();
    k_scan3<<<NB_SCAN, 256>>>();
    k_gemm0<<<(NN + 63) / 64, 256>>>(x, w_feat);
    k_fill<<<(ENT + 255) / 256, 256>>>(ei);

    // GNFE: aggregate transformed features (+bias, relu)
    k_agg56<<<NPAD / 8, 256>>>(p_x1, p_hB, b_feat, 1);

    for (int m = 0; m < NL; m++) {
        for (int i = 0; i < NL; i++) {
            int li = m * NL + i;
            const float* Wt = gat_w + li * DH * DH;
            const float* as = gat_as + li * NH * PH;
            const float* ad = gat_ad + li * NH * PH;
            if (i == 0) {
                if (m == 0) {
                    k_agg56<<<NPAD / 8, 256>>>(p_hB, p_agg, (const float*)0, 0);
                    k_fused<D0><<<NPAD / 32, 128>>>(p_agg, gcn0_w, gcn0_b,
                                                    (const float*)0, Wt, as, ad);
                } else {
                    k_prep<<<1, 128>>>(mas_w + (m - 1) * PH * D0,
                                       mas_b + (m - 1) * D0,
                                       gcn0_w + m * D0 * DH);
                    k_agg16<<<NPAD / 16, 256>>>(p_hA, p_agg);
                    k_fused<PH><<<NPAD / 32, 128>>>(p_agg, p_wf, gcn0_b + m * DH,
                                                    p_bvec, Wt, as, ad);
                }
            } else {
                k_agg16<<<NPAD / 16, 256>>>(p_hA, p_agg);
                k_fused<PH><<<NPAD / 32, 128>>>(
                    p_agg, gcn_w + (m * (NL - 1) + (i - 1)) * PH * DH,
                    gcn_b + (m * (NL - 1) + (i - 1)) * DH,
                    (const float*)0, Wt, as, ad);
            }
            k_gat_edge<<<(NN * 32 + 255) / 256, 256>>>(gat_b + li * PH);
        }
    }
    k_prep_out<<<1, 32>>>(mas_w + 2 * PH * D0, mas_b + 2 * D0, out_w, out_b);
    k_masout<<<(NN * NC + 255) / 256, 256>>>(out);
}